// round 15
// baseline (speedup 1.0000x reference)
#include <cuda_runtime.h>
#include <cuda_bf16.h>
#include <cuda_fp16.h>
#include <cstdint>

#define N_MAX 100352
#define E_MAX 1000000
#define HID 64

// ---------------- device scratch ----------------
__device__ float  g_H  [100000 * HID];   // h / residual (fp32)
__device__ __half g_HWh[100000 * HID];   // dinv[row] * (h @ w)  (fp16, pre-scaled)
__device__ float g_dinv[N_MAX];
__device__ int   g_hist[N_MAX];
__device__ int   g_offs[N_MAX];
__device__ int   g_cur [N_MAX];
__device__ int   g_part[256];
__device__ int   g_esrc[E_MAX];
__device__ int   g_is64;

// ---------------- edge access ----------------
__device__ __forceinline__ int edge_at(const void* ei, int idx) {
    if (g_is64) return (int)((const long long*)ei)[idx];
    return ((const int*)ei)[idx];
}

// ---------------- zero hist + dtype detect (merged) ----------------
__global__ void k_zero_detect(const unsigned long long* __restrict__ ei, int n) {
    int i = blockIdx.x * blockDim.x + threadIdx.x;
    if (i < n) g_hist[i] = 0;
    if (blockIdx.x == 0) {
        int local = 0;
        for (int j = threadIdx.x; j < 1024; j += blockDim.x)
            if ((ei[j] >> 32) != 0ull) local = 1;
        int any = __syncthreads_or(local);
        if (threadIdx.x == 0) g_is64 = (any == 0);
    }
}

__global__ void k_hist(const void* __restrict__ ei, int E) {
    int e = blockIdx.x * blockDim.x + threadIdx.x;
    if (e < E) atomicAdd(&g_hist[edge_at(ei, E + e)], 1);
}

// ---------------- scan1 (+dinv merged) ----------------
__global__ void k_scan1(int n) {
    int idx = blockIdx.x * 512 + threadIdx.x;
    int v = (idx < n) ? g_hist[idx] : 0;
    if (idx < n) g_dinv[idx] = rsqrtf((float)v + 1.0f);
    int lane = threadIdx.x & 31, wid = threadIdx.x >> 5;
    int inc = v;
    #pragma unroll
    for (int o = 1; o < 32; o <<= 1) {
        int t = __shfl_up_sync(0xffffffffu, inc, o);
        if (lane >= o) inc += t;
    }
    __shared__ int wsum[16];
    if (lane == 31) wsum[wid] = inc;
    __syncthreads();
    if (wid == 0) {
        int s = (lane < 16) ? wsum[lane] : 0;
        #pragma unroll
        for (int o = 1; o < 16; o <<= 1) {
            int t = __shfl_up_sync(0xffffffffu, s, o);
            if (lane >= o) s += t;
        }
        if (lane < 16) wsum[lane] = s;
    }
    __syncthreads();
    int base = (wid > 0) ? wsum[wid - 1] : 0;
    if (idx < n) g_offs[idx] = base + inc - v;
    if (threadIdx.x == 0) g_part[blockIdx.x] = wsum[15];
}

__global__ void k_scan2(int nb) {
    int t = threadIdx.x;
    int v = (t < nb) ? g_part[t] : 0;
    int lane = t & 31, wid = t >> 5;
    int inc = v;
    #pragma unroll
    for (int o = 1; o < 32; o <<= 1) {
        int s = __shfl_up_sync(0xffffffffu, inc, o);
        if (lane >= o) inc += s;
    }
    __shared__ int wsum[8];
    if (lane == 31) wsum[wid] = inc;
    __syncthreads();
    if (wid == 0) {
        int s = (lane < 8) ? wsum[lane] : 0;
        #pragma unroll
        for (int o = 1; o < 8; o <<= 1) {
            int u = __shfl_up_sync(0xffffffffu, s, o);
            if (lane >= o) s += u;
        }
        if (lane < 8) wsum[lane] = s;
    }
    __syncthreads();
    int base = (wid > 0) ? wsum[wid - 1] : 0;
    if (t < nb) g_part[t] = base + inc - v;
}

__global__ void k_scan3(int n) {
    int idx = blockIdx.x * 512 + threadIdx.x;
    if (idx < n) {
        int o = g_offs[idx] + g_part[blockIdx.x];
        g_offs[idx] = o;
        g_cur[idx]  = o;
    }
}

__global__ void k_place(const void* __restrict__ ei, int E) {
    int e = blockIdx.x * blockDim.x + threadIdx.x;
    if (e < E) {
        int s = edge_at(ei, e);
        int d = edge_at(ei, E + e);
        int pos = atomicAdd(&g_cur[d], 1);
        g_esrc[pos] = s;
    }
}

// ---------------- bf16 split helpers ----------------
__device__ __forceinline__ unsigned short bits_of(__nv_bfloat16 h) {
    return *(unsigned short*)&h;
}
__device__ __forceinline__ void split2(float x, float y, unsigned& hi, unsigned& lo) {
    __nv_bfloat16 hx = __float2bfloat16_rn(x);
    __nv_bfloat16 hy = __float2bfloat16_rn(y);
    __nv_bfloat16 lx = __float2bfloat16_rn(x - __bfloat162float(hx));
    __nv_bfloat16 ly = __float2bfloat16_rn(y - __bfloat162float(hy));
    hi = (unsigned)bits_of(hx) | ((unsigned)bits_of(hy) << 16);
    lo = (unsigned)bits_of(lx) | ((unsigned)bits_of(ly) << 16);
}

__device__ __forceinline__ void mma16816(float* c, const unsigned* a,
                                         unsigned b0, unsigned b1) {
    asm volatile(
        "mma.sync.aligned.m16n8k16.row.col.f32.bf16.bf16.f32 "
        "{%0,%1,%2,%3}, {%4,%5,%6,%7}, {%8,%9}, {%0,%1,%2,%3};"
        : "+f"(c[0]), "+f"(c[1]), "+f"(c[2]), "+f"(c[3])
        : "r"(a[0]), "r"(a[1]), "r"(a[2]), "r"(a[3]), "r"(b0), "r"(b1));
}

// ---------------- tensor GEMM (exact R11 version) ----------------
__global__ __launch_bounds__(256) void k_tgemm(
    const float* __restrict__ Aext, const float* __restrict__ W,
    const float* __restrict__ bias, int dst, int n, int K)
{
    const float* A = Aext ? Aext : (const float*)g_H;

    __shared__ __nv_bfloat16 Wh[64][72];
    __shared__ __nv_bfloat16 Wl[64][72];

    int tid = threadIdx.x;
    if (K == 64) {
        #pragma unroll
        for (int u = 0; u < 16; u++) {
            int i = tid * 16 + u;
            int kk = i >> 6, nn = i & 63;
            float wv = W[i];
            __nv_bfloat16 h = __float2bfloat16_rn(wv);
            __nv_bfloat16 l = __float2bfloat16_rn(wv - __bfloat162float(h));
            Wh[nn][kk] = h; Wl[nn][kk] = l;
        }
    }

    int row_base = blockIdx.x * 128;
    int warp = tid >> 5, lane = tid & 31;
    int r = lane >> 2, q = lane & 3;
    int row0 = row_base + warp * 16 + r;
    int rowA0 = min(row0, n - 1);
    int rowA1 = min(row0 + 8, n - 1);

    float c[8][4];
    #pragma unroll
    for (int nf = 0; nf < 8; nf++)
        #pragma unroll
        for (int j = 0; j < 4; j++) c[nf][j] = 0.0f;

    int khalves = K >> 6;
    for (int kh = 0; kh < khalves; kh++) {
        if (K == 128) {
            __syncthreads();
            for (int i = tid; i < 64 * 64; i += 256) {
                int kk = i >> 6, nn = i & 63;
                float wv = W[(kh * 64 + kk) * 64 + nn];
                __nv_bfloat16 h = __float2bfloat16_rn(wv);
                __nv_bfloat16 l = __float2bfloat16_rn(wv - __bfloat162float(h));
                Wh[nn][kk] = h; Wl[nn][kk] = l;
            }
        }
        __syncthreads();

        #pragma unroll
        for (int kc = 0; kc < 4; kc++) {
            int kbase = kh * 64 + kc * 16 + q * 2;
            const float* p0 = A + (size_t)rowA0 * K + kbase;
            const float* p1 = A + (size_t)rowA1 * K + kbase;
            float2 v0 = *(const float2*)p0;
            float2 v1 = *(const float2*)p1;
            float2 v2 = *(const float2*)(p0 + 8);
            float2 v3 = *(const float2*)(p1 + 8);
            unsigned ah[4], al[4];
            split2(v0.x, v0.y, ah[0], al[0]);
            split2(v1.x, v1.y, ah[1], al[1]);
            split2(v2.x, v2.y, ah[2], al[2]);
            split2(v3.x, v3.y, ah[3], al[3]);

            #pragma unroll
            for (int nf = 0; nf < 8; nf++) {
                int bn = nf * 8 + r;
                int bk = kc * 16 + q * 2;
                unsigned bh0 = *(const unsigned*)&Wh[bn][bk];
                unsigned bh1 = *(const unsigned*)&Wh[bn][bk + 8];
                unsigned bl0 = *(const unsigned*)&Wl[bn][bk];
                unsigned bl1 = *(const unsigned*)&Wl[bn][bk + 8];
                mma16816(c[nf], ah, bh0, bh1);
                mma16816(c[nf], al, bh0, bh1);
                mma16816(c[nf], ah, bl0, bl1);
            }
        }
    }

    if (dst == 0) {
        #pragma unroll
        for (int nf = 0; nf < 8; nf++) {
            int col = nf * 8 + q * 2;
            float bx = 0.f, by = 0.f;
            if (bias) { float2 bb = *(const float2*)(bias + col); bx = bb.x; by = bb.y; }
            if (row0 < n)
                *(float2*)(g_H + (size_t)row0 * 64 + col) =
                    make_float2(c[nf][0] + bx, c[nf][1] + by);
            if (row0 + 8 < n)
                *(float2*)(g_H + (size_t)(row0 + 8) * 64 + col) =
                    make_float2(c[nf][2] + bx, c[nf][3] + by);
        }
    } else {
        __half2* Cp = (__half2*)g_HWh;
        float sc0 = (row0 < n) ? g_dinv[row0] : 0.f;
        float sc1 = (row0 + 8 < n) ? g_dinv[row0 + 8] : 0.f;
        #pragma unroll
        for (int nf = 0; nf < 8; nf++) {
            int colh = nf * 4 + q;
            if (row0 < n)
                Cp[(size_t)row0 * 32 + colh] =
                    __floats2half2_rn(c[nf][0] * sc0, c[nf][1] * sc0);
            if (row0 + 8 < n)
                Cp[(size_t)(row0 + 8) * 32 + colh] =
                    __floats2half2_rn(c[nf][2] * sc1, c[nf][3] * sc1);
        }
    }
}

// ---------------- fused aggregate + bias + LN (+ReLU+residual) ----------
// 2 nodes / warp, 16 lanes per node; within a group, lanes 0-7 process even
// edges, lanes 8-15 odd edges (2 edges per LDG instruction); 2-deep unroll
// => 4 edges consumed per iteration per node, halving the latency chain.
__global__ __launch_bounds__(256) void k_agg(
    const float* __restrict__ bias, const float* __restrict__ gma,
    const float* __restrict__ beta, float* __restrict__ out_ext,
    int n, int relu_res)
{
    int warp = (blockIdx.x * blockDim.x + threadIdx.x) >> 5;
    int lane = threadIdx.x & 31;
    int grp = lane >> 4;            // 0..1 : node within warp
    int sub16 = lane & 15;
    int half = sub16 >> 3;          // 0..1 : edge parity within node
    int sub8 = sub16 & 7;           // 0..7 : 16B chunk within row
    int node = warp * 2 + grp;
    bool valid = (node < n);
    int nodeL = valid ? node : (n - 1);

    float* out = out_ext ? out_ext : (float*)g_H;
    const uint4* HW4 = (const uint4*)g_HWh;     // 8 uint4 per row

    // chain A gets the self term (only on half 0 so it isn't double-counted)
    float2 aA[4], aB[4];
    #pragma unroll
    for (int i = 0; i < 4; i++) { aA[i] = make_float2(0.f, 0.f); aB[i] = aA[i]; }
    if (half == 0) {
        uint4 sv = HW4[(size_t)nodeL * 8 + sub8];
        #pragma unroll
        for (int i = 0; i < 4; i++) aA[i] = __half22float2(((const __half2*)&sv)[i]);
    }

    int e = valid ? g_offs[nodeL] : 0;
    int e_end = valid ? (e + g_hist[nodeL]) : 0;

    // main loop: 4 edges per iteration (this half takes e+half and e+2+half)
    for (; e + 4 <= e_end; e += 4) {
        int s0 = g_esrc[e + half];
        int s1 = g_esrc[e + 2 + half];
        uint4 u0 = HW4[(size_t)s0 * 8 + sub8];
        uint4 u1 = HW4[(size_t)s1 * 8 + sub8];
        #pragma unroll
        for (int i = 0; i < 4; i++) {
            float2 f0 = __half22float2(((const __half2*)&u0)[i]);
            float2 f1 = __half22float2(((const __half2*)&u1)[i]);
            aA[i].x += f0.x; aA[i].y += f0.y;
            aB[i].x += f1.x; aB[i].y += f1.y;
        }
    }
    // remainder 0..3 edges
    int rem = e_end - e;
    if (rem > half) {                     // half0: rem>=1, half1: rem>=2
        int s0 = g_esrc[e + half];
        uint4 u0 = HW4[(size_t)s0 * 8 + sub8];
        #pragma unroll
        for (int i = 0; i < 4; i++) {
            float2 f0 = __half22float2(((const __half2*)&u0)[i]);
            aA[i].x += f0.x; aA[i].y += f0.y;
        }
    }
    if (rem == 3 && half == 0) {
        int s1 = g_esrc[e + 2];
        uint4 u1 = HW4[(size_t)s1 * 8 + sub8];
        #pragma unroll
        for (int i = 0; i < 4; i++) {
            float2 f1 = __half22float2(((const __half2*)&u1)[i]);
            aB[i].x += f1.x; aB[i].y += f1.y;
        }
    }

    // combine chains, then combine halves (lane ^ 8 holds the other parity)
    float v[8];
    #pragma unroll
    for (int i = 0; i < 4; i++) {
        v[2 * i]     = aA[i].x + aB[i].x;
        v[2 * i + 1] = aA[i].y + aB[i].y;
    }
    #pragma unroll
    for (int i = 0; i < 8; i++) v[i] += __shfl_xor_sync(0xffffffffu, v[i], 8);

    float di = g_dinv[nodeL];
    #pragma unroll
    for (int i = 0; i < 8; i++) v[i] *= di;

    // + bias (lane covers cols sub8*8 .. sub8*8+7)
    float4 b0 = ((const float4*)bias)[sub8 * 2];
    float4 b1 = ((const float4*)bias)[sub8 * 2 + 1];
    v[0] += b0.x; v[1] += b0.y; v[2] += b0.z; v[3] += b0.w;
    v[4] += b1.x; v[5] += b1.y; v[6] += b1.z; v[7] += b1.w;

    // LayerNorm over 64 cols: local 8 + reduce over sub8 octet (xor 1,2,4)
    float sum = ((v[0] + v[1]) + (v[2] + v[3])) + ((v[4] + v[5]) + (v[6] + v[7]));
    #pragma unroll
    for (int o = 4; o; o >>= 1) sum += __shfl_xor_sync(0xffffffffu, sum, o);
    float mu = sum * (1.0f / 64.0f);
    float vs = 0.f;
    #pragma unroll
    for (int i = 0; i < 8; i++) { v[i] -= mu; vs += v[i] * v[i]; }
    #pragma unroll
    for (int o = 4; o; o >>= 1) vs += __shfl_xor_sync(0xffffffffu, vs, o);
    float rstd = rsqrtf(vs * (1.0f / 64.0f) + 1e-5f);

    if (!valid || half != 0) return;     // half 0 lanes write the row

    float4 g0 = ((const float4*)gma)[sub8 * 2];
    float4 g1 = ((const float4*)gma)[sub8 * 2 + 1];
    float4 t0 = ((const float4*)beta)[sub8 * 2];
    float4 t1 = ((const float4*)beta)[sub8 * 2 + 1];
    float o0x = v[0] * rstd * g0.x + t0.x, o0y = v[1] * rstd * g0.y + t0.y;
    float o0z = v[2] * rstd * g0.z + t0.z, o0w = v[3] * rstd * g0.w + t0.w;
    float o1x = v[4] * rstd * g1.x + t1.x, o1y = v[5] * rstd * g1.y + t1.y;
    float o1z = v[6] * rstd * g1.z + t1.z, o1w = v[7] * rstd * g1.w + t1.w;

    if (relu_res) {
        float4* Hrow = (float4*)(g_H + (size_t)node * 64) + sub8 * 2;
        float4 r0 = Hrow[0], r1 = Hrow[1];
        o0x = fmaxf(o0x, 0.f) + r0.x; o0y = fmaxf(o0y, 0.f) + r0.y;
        o0z = fmaxf(o0z, 0.f) + r0.z; o0w = fmaxf(o0w, 0.f) + r0.w;
        o1x = fmaxf(o1x, 0.f) + r1.x; o1y = fmaxf(o1y, 0.f) + r1.y;
        o1z = fmaxf(o1z, 0.f) + r1.z; o1w = fmaxf(o1w, 0.f) + r1.w;
        Hrow[0] = make_float4(o0x, o0y, o0z, o0w);
        Hrow[1] = make_float4(o1x, o1y, o1z, o1w);
    } else {
        float4* Orow = (float4*)(out + (size_t)node * 64) + sub8 * 2;
        Orow[0] = make_float4(o0x, o0y, o0z, o0w);
        Orow[1] = make_float4(o1x, o1y, o1z, o1w);
    }
}

// ---------------- launch ----------------
extern "C" void kernel_launch(void* const* d_in, const int* in_sizes, int n_in,
                              void* d_out, int out_size)
{
    const float* x      = (const float*)d_in[0];
    const void*  ei     = d_in[1];
    const float* proj_w = (const float*)d_in[2];
    const float* proj_b = (const float*)d_in[3];
    const float* w[3]  = { (const float*)d_in[4],  (const float*)d_in[8],  (const float*)d_in[12] };
    const float* b[3]  = { (const float*)d_in[5],  (const float*)d_in[9],  (const float*)d_in[13] };
    const float* gm[3] = { (const float*)d_in[6],  (const float*)d_in[10], (const float*)d_in[14] };
    const float* bt[3] = { (const float*)d_in[7],  (const float*)d_in[11], (const float*)d_in[15] };

    int n = in_sizes[0] / 128;    // 100000
    int E = in_sizes[1] / 2;      // 1000000
    float* out = (float*)d_out;

    int nb512 = (n + 511) / 512;
    int gemm_blocks = (n + 127) / 128;
    int agg_blocks = (n + 15) / 16;     // 2 nodes per warp, 8 warps per block

    cudaStream_t s2;
    cudaEvent_t evFork, evScan1, evJoin;
    bool forked = (cudaStreamCreateWithFlags(&s2, cudaStreamNonBlocking) == cudaSuccess);
    if (forked) {
        cudaEventCreateWithFlags(&evFork,  cudaEventDisableTiming);
        cudaEventCreateWithFlags(&evScan1, cudaEventDisableTiming);
        cudaEventCreateWithFlags(&evJoin,  cudaEventDisableTiming);
        cudaEventRecord(evFork, 0);
        cudaStreamWaitEvent(s2, evFork, 0);
    }
    cudaStream_t sp = forked ? s2 : (cudaStream_t)0;

    k_zero_detect<<<(n + 255) / 256, 256>>>((const unsigned long long*)ei, n);
    k_hist<<<(E + 255) / 256, 256>>>(ei, E);
    k_scan1<<<nb512, 512>>>(n);                         // produces g_dinv
    if (forked) cudaEventRecord(evScan1, 0);

    // fork branch: proj GEMM, then layer-0 GEMM (needs g_H + g_dinv, not edges)
    k_tgemm<<<gemm_blocks, 256, 0, sp>>>(x, proj_w, proj_b, /*dst=*/0, n, 128);
    if (forked) cudaStreamWaitEvent(s2, evScan1, 0);
    k_tgemm<<<gemm_blocks, 256, 0, sp>>>(nullptr, w[0], nullptr, /*dst=*/1, n, 64);

    k_scan2<<<1, 256>>>(nb512);
    k_scan3<<<nb512, 512>>>(n);
    k_place<<<(E + 255) / 256, 256>>>(ei, E);

    if (forked) {
        cudaEventRecord(evJoin, s2);
        cudaStreamWaitEvent(0, evJoin, 0);
    }

    for (int l = 0; l < 3; l++) {
        if (l > 0)
            k_tgemm<<<gemm_blocks, 256>>>(nullptr, w[l], nullptr, /*dst=*/1, n, 64);
        float* dst = (l < 2) ? nullptr : out;
        k_agg<<<agg_blocks, 256>>>(b[l], gm[l], bt[l], dst, n, (l < 2) ? 1 : 0);
    }

    if (forked) {
        cudaStreamDestroy(s2);
        cudaEventDestroy(evFork);
        cudaEventDestroy(evScan1);
        cudaEventDestroy(evJoin);
    }
}

// round 16
// speedup vs baseline: 1.1098x; 1.1098x over previous
#include <cuda_runtime.h>
#include <cuda_bf16.h>
#include <cuda_fp16.h>
#include <cstdint>

#define N_MAX 100352
#define E_MAX 1000000
#define HID 64

// ---------------- device scratch ----------------
__device__ float  g_H  [100000 * HID];   // h / residual (fp32)
__device__ __half g_HWh[100000 * HID];   // dinv[row] * (h @ w)  (fp16, pre-scaled)
__device__ float g_dinv[N_MAX];
__device__ int   g_hist[N_MAX];
__device__ int   g_offs[N_MAX];
__device__ int   g_cur [N_MAX];
__device__ int   g_part[256];
__device__ int   g_esrc[E_MAX];
__device__ int   g_is64;

// ---------------- edge access ----------------
__device__ __forceinline__ int edge_at(const void* ei, int idx) {
    if (g_is64) return (int)((const long long*)ei)[idx];
    return ((const int*)ei)[idx];
}

// ---------------- zero hist + dtype detect (merged) ----------------
__global__ void k_zero_detect(const unsigned long long* __restrict__ ei, int n) {
    int i = blockIdx.x * blockDim.x + threadIdx.x;
    if (i < n) g_hist[i] = 0;
    if (blockIdx.x == 0) {
        int local = 0;
        for (int j = threadIdx.x; j < 1024; j += blockDim.x)
            if ((ei[j] >> 32) != 0ull) local = 1;
        int any = __syncthreads_or(local);
        if (threadIdx.x == 0) g_is64 = (any == 0);
    }
}

__global__ void k_hist(const void* __restrict__ ei, int E) {
    int e = blockIdx.x * blockDim.x + threadIdx.x;
    if (e < E) atomicAdd(&g_hist[edge_at(ei, E + e)], 1);
}

// ---------------- scan1 (+dinv merged) ----------------
__global__ void k_scan1(int n) {
    int idx = blockIdx.x * 512 + threadIdx.x;
    int v = (idx < n) ? g_hist[idx] : 0;
    if (idx < n) g_dinv[idx] = rsqrtf((float)v + 1.0f);
    int lane = threadIdx.x & 31, wid = threadIdx.x >> 5;
    int inc = v;
    #pragma unroll
    for (int o = 1; o < 32; o <<= 1) {
        int t = __shfl_up_sync(0xffffffffu, inc, o);
        if (lane >= o) inc += t;
    }
    __shared__ int wsum[16];
    if (lane == 31) wsum[wid] = inc;
    __syncthreads();
    if (wid == 0) {
        int s = (lane < 16) ? wsum[lane] : 0;
        #pragma unroll
        for (int o = 1; o < 16; o <<= 1) {
            int t = __shfl_up_sync(0xffffffffu, s, o);
            if (lane >= o) s += t;
        }
        if (lane < 16) wsum[lane] = s;
    }
    __syncthreads();
    int base = (wid > 0) ? wsum[wid - 1] : 0;
    if (idx < n) g_offs[idx] = base + inc - v;
    if (threadIdx.x == 0) g_part[blockIdx.x] = wsum[15];
}

// ---------------- scan2+scan3 merged: each block reduces g_part[0..blk) ----
__global__ void k_scan23(int n) {
    int blk = blockIdx.x;
    int idx = blk * 512 + threadIdx.x;
    __shared__ int s_base;
    int lane = threadIdx.x & 31;
    if (threadIdx.x < 32) {
        int acc = 0;
        for (int j = lane; j < blk; j += 32) acc += g_part[j];
        #pragma unroll
        for (int o = 16; o; o >>= 1) acc += __shfl_xor_sync(0xffffffffu, acc, o);
        if (lane == 0) s_base = acc;
    }
    __syncthreads();
    if (idx < n) {
        int o = g_offs[idx] + s_base;
        g_offs[idx] = o;
        g_cur[idx]  = o;
    }
}

__global__ void k_place(const void* __restrict__ ei, int E) {
    int e = blockIdx.x * blockDim.x + threadIdx.x;
    if (e < E) {
        int s = edge_at(ei, e);
        int d = edge_at(ei, E + e);
        int pos = atomicAdd(&g_cur[d], 1);
        g_esrc[pos] = s;
    }
}

// ---------------- bf16 split helpers ----------------
__device__ __forceinline__ unsigned short bits_of(__nv_bfloat16 h) {
    return *(unsigned short*)&h;
}
__device__ __forceinline__ void split2(float x, float y, unsigned& hi, unsigned& lo) {
    __nv_bfloat16 hx = __float2bfloat16_rn(x);
    __nv_bfloat16 hy = __float2bfloat16_rn(y);
    __nv_bfloat16 lx = __float2bfloat16_rn(x - __bfloat162float(hx));
    __nv_bfloat16 ly = __float2bfloat16_rn(y - __bfloat162float(hy));
    hi = (unsigned)bits_of(hx) | ((unsigned)bits_of(hy) << 16);
    lo = (unsigned)bits_of(lx) | ((unsigned)bits_of(ly) << 16);
}

__device__ __forceinline__ void mma16816(float* c, const unsigned* a,
                                         unsigned b0, unsigned b1) {
    asm volatile(
        "mma.sync.aligned.m16n8k16.row.col.f32.bf16.bf16.f32 "
        "{%0,%1,%2,%3}, {%4,%5,%6,%7}, {%8,%9}, {%0,%1,%2,%3};"
        : "+f"(c[0]), "+f"(c[1]), "+f"(c[2]), "+f"(c[3])
        : "r"(a[0]), "r"(a[1]), "r"(a[2]), "r"(a[3]), "r"(b0), "r"(b1));
}

// ---------------- tensor GEMM (exact R11 version) ----------------
__global__ __launch_bounds__(256) void k_tgemm(
    const float* __restrict__ Aext, const float* __restrict__ W,
    const float* __restrict__ bias, int dst, int n, int K)
{
    const float* A = Aext ? Aext : (const float*)g_H;

    __shared__ __nv_bfloat16 Wh[64][72];
    __shared__ __nv_bfloat16 Wl[64][72];

    int tid = threadIdx.x;
    if (K == 64) {
        #pragma unroll
        for (int u = 0; u < 16; u++) {
            int i = tid * 16 + u;
            int kk = i >> 6, nn = i & 63;
            float wv = W[i];
            __nv_bfloat16 h = __float2bfloat16_rn(wv);
            __nv_bfloat16 l = __float2bfloat16_rn(wv - __bfloat162float(h));
            Wh[nn][kk] = h; Wl[nn][kk] = l;
        }
    }

    int row_base = blockIdx.x * 128;
    int warp = tid >> 5, lane = tid & 31;
    int r = lane >> 2, q = lane & 3;
    int row0 = row_base + warp * 16 + r;
    int rowA0 = min(row0, n - 1);
    int rowA1 = min(row0 + 8, n - 1);

    float c[8][4];
    #pragma unroll
    for (int nf = 0; nf < 8; nf++)
        #pragma unroll
        for (int j = 0; j < 4; j++) c[nf][j] = 0.0f;

    int khalves = K >> 6;
    for (int kh = 0; kh < khalves; kh++) {
        if (K == 128) {
            __syncthreads();
            for (int i = tid; i < 64 * 64; i += 256) {
                int kk = i >> 6, nn = i & 63;
                float wv = W[(kh * 64 + kk) * 64 + nn];
                __nv_bfloat16 h = __float2bfloat16_rn(wv);
                __nv_bfloat16 l = __float2bfloat16_rn(wv - __bfloat162float(h));
                Wh[nn][kk] = h; Wl[nn][kk] = l;
            }
        }
        __syncthreads();

        #pragma unroll
        for (int kc = 0; kc < 4; kc++) {
            int kbase = kh * 64 + kc * 16 + q * 2;
            const float* p0 = A + (size_t)rowA0 * K + kbase;
            const float* p1 = A + (size_t)rowA1 * K + kbase;
            float2 v0 = *(const float2*)p0;
            float2 v1 = *(const float2*)p1;
            float2 v2 = *(const float2*)(p0 + 8);
            float2 v3 = *(const float2*)(p1 + 8);
            unsigned ah[4], al[4];
            split2(v0.x, v0.y, ah[0], al[0]);
            split2(v1.x, v1.y, ah[1], al[1]);
            split2(v2.x, v2.y, ah[2], al[2]);
            split2(v3.x, v3.y, ah[3], al[3]);

            #pragma unroll
            for (int nf = 0; nf < 8; nf++) {
                int bn = nf * 8 + r;
                int bk = kc * 16 + q * 2;
                unsigned bh0 = *(const unsigned*)&Wh[bn][bk];
                unsigned bh1 = *(const unsigned*)&Wh[bn][bk + 8];
                unsigned bl0 = *(const unsigned*)&Wl[bn][bk];
                unsigned bl1 = *(const unsigned*)&Wl[bn][bk + 8];
                mma16816(c[nf], ah, bh0, bh1);
                mma16816(c[nf], al, bh0, bh1);
                mma16816(c[nf], ah, bl0, bl1);
            }
        }
    }

    if (dst == 0) {
        #pragma unroll
        for (int nf = 0; nf < 8; nf++) {
            int col = nf * 8 + q * 2;
            float bx = 0.f, by = 0.f;
            if (bias) { float2 bb = *(const float2*)(bias + col); bx = bb.x; by = bb.y; }
            if (row0 < n)
                *(float2*)(g_H + (size_t)row0 * 64 + col) =
                    make_float2(c[nf][0] + bx, c[nf][1] + by);
            if (row0 + 8 < n)
                *(float2*)(g_H + (size_t)(row0 + 8) * 64 + col) =
                    make_float2(c[nf][2] + bx, c[nf][3] + by);
        }
    } else {
        __half2* Cp = (__half2*)g_HWh;
        float sc0 = (row0 < n) ? g_dinv[row0] : 0.f;
        float sc1 = (row0 + 8 < n) ? g_dinv[row0 + 8] : 0.f;
        #pragma unroll
        for (int nf = 0; nf < 8; nf++) {
            int colh = nf * 4 + q;
            if (row0 < n)
                Cp[(size_t)row0 * 32 + colh] =
                    __floats2half2_rn(c[nf][0] * sc0, c[nf][1] * sc0);
            if (row0 + 8 < n)
                Cp[(size_t)(row0 + 8) * 32 + colh] =
                    __floats2half2_rn(c[nf][2] * sc1, c[nf][3] * sc1);
        }
    }
}

// ---------------- fused aggregate + bias + LN (+ReLU+residual) ----------
// 4 nodes / warp, 8 lanes per node, 2 edges per group-iteration (R11 proven)
__global__ __launch_bounds__(256) void k_agg(
    const float* __restrict__ bias, const float* __restrict__ gma,
    const float* __restrict__ beta, float* __restrict__ out_ext,
    int n, int relu_res)
{
    int warp = (blockIdx.x * blockDim.x + threadIdx.x) >> 5;
    int lane = threadIdx.x & 31;
    int grp = lane >> 3, sub = lane & 7;
    int node = warp * 4 + grp;
    bool valid = (node < n);
    int nodeL = valid ? node : (n - 1);

    float* out = out_ext ? out_ext : (float*)g_H;
    const uint4* HW4 = (const uint4*)g_HWh;

    uint4 sv = HW4[(size_t)nodeL * 8 + sub];
    float2 aA[4], aB[4];
    #pragma unroll
    for (int i = 0; i < 4; i++) {
        aA[i] = __half22float2(((const __half2*)&sv)[i]);
        aB[i] = make_float2(0.f, 0.f);
    }

    int e = valid ? g_offs[nodeL] : 0;
    int e_end = valid ? (e + g_hist[nodeL]) : 0;
    for (; e + 2 <= e_end; e += 2) {
        int s0 = g_esrc[e];
        int s1 = g_esrc[e + 1];
        uint4 u0 = HW4[(size_t)s0 * 8 + sub];
        uint4 u1 = HW4[(size_t)s1 * 8 + sub];
        #pragma unroll
        for (int i = 0; i < 4; i++) {
            float2 f0 = __half22float2(((const __half2*)&u0)[i]);
            float2 f1 = __half22float2(((const __half2*)&u1)[i]);
            aA[i].x += f0.x; aA[i].y += f0.y;
            aB[i].x += f1.x; aB[i].y += f1.y;
        }
    }
    if (e < e_end) {
        int s0 = g_esrc[e];
        uint4 u0 = HW4[(size_t)s0 * 8 + sub];
        #pragma unroll
        for (int i = 0; i < 4; i++) {
            float2 f0 = __half22float2(((const __half2*)&u0)[i]);
            aA[i].x += f0.x; aA[i].y += f0.y;
        }
    }

    float di = g_dinv[nodeL];
    float v[8];
    #pragma unroll
    for (int i = 0; i < 4; i++) {
        v[2 * i]     = (aA[i].x + aB[i].x) * di;
        v[2 * i + 1] = (aA[i].y + aB[i].y) * di;
    }

    float4 b0 = ((const float4*)bias)[sub * 2];
    float4 b1 = ((const float4*)bias)[sub * 2 + 1];
    v[0] += b0.x; v[1] += b0.y; v[2] += b0.z; v[3] += b0.w;
    v[4] += b1.x; v[5] += b1.y; v[6] += b1.z; v[7] += b1.w;

    float sum = ((v[0] + v[1]) + (v[2] + v[3])) + ((v[4] + v[5]) + (v[6] + v[7]));
    #pragma unroll
    for (int o = 4; o; o >>= 1) sum += __shfl_xor_sync(0xffffffffu, sum, o);
    float mu = sum * (1.0f / 64.0f);
    float vs = 0.f;
    #pragma unroll
    for (int i = 0; i < 8; i++) { v[i] -= mu; vs += v[i] * v[i]; }
    #pragma unroll
    for (int o = 4; o; o >>= 1) vs += __shfl_xor_sync(0xffffffffu, vs, o);
    float rstd = rsqrtf(vs * (1.0f / 64.0f) + 1e-5f);

    float4 g0 = ((const float4*)gma)[sub * 2];
    float4 g1 = ((const float4*)gma)[sub * 2 + 1];
    float4 t0 = ((const float4*)beta)[sub * 2];
    float4 t1 = ((const float4*)beta)[sub * 2 + 1];
    float o0x = v[0] * rstd * g0.x + t0.x, o0y = v[1] * rstd * g0.y + t0.y;
    float o0z = v[2] * rstd * g0.z + t0.z, o0w = v[3] * rstd * g0.w + t0.w;
    float o1x = v[4] * rstd * g1.x + t1.x, o1y = v[5] * rstd * g1.y + t1.y;
    float o1z = v[6] * rstd * g1.z + t1.z, o1w = v[7] * rstd * g1.w + t1.w;

    if (!valid) return;

    if (relu_res) {
        float4* Hrow = (float4*)(g_H + (size_t)node * 64) + sub * 2;
        float4 r0 = Hrow[0], r1 = Hrow[1];
        o0x = fmaxf(o0x, 0.f) + r0.x; o0y = fmaxf(o0y, 0.f) + r0.y;
        o0z = fmaxf(o0z, 0.f) + r0.z; o0w = fmaxf(o0w, 0.f) + r0.w;
        o1x = fmaxf(o1x, 0.f) + r1.x; o1y = fmaxf(o1y, 0.f) + r1.y;
        o1z = fmaxf(o1z, 0.f) + r1.z; o1w = fmaxf(o1w, 0.f) + r1.w;
        Hrow[0] = make_float4(o0x, o0y, o0z, o0w);
        Hrow[1] = make_float4(o1x, o1y, o1z, o1w);
    } else {
        float4* Orow = (float4*)(out + (size_t)node * 64) + sub * 2;
        Orow[0] = make_float4(o0x, o0y, o0z, o0w);
        Orow[1] = make_float4(o1x, o1y, o1z, o1w);
    }
}

// ---------------- launch ----------------
extern "C" void kernel_launch(void* const* d_in, const int* in_sizes, int n_in,
                              void* d_out, int out_size)
{
    const float* x      = (const float*)d_in[0];
    const void*  ei     = d_in[1];
    const float* proj_w = (const float*)d_in[2];
    const float* proj_b = (const float*)d_in[3];
    const float* w[3]  = { (const float*)d_in[4],  (const float*)d_in[8],  (const float*)d_in[12] };
    const float* b[3]  = { (const float*)d_in[5],  (const float*)d_in[9],  (const float*)d_in[13] };
    const float* gm[3] = { (const float*)d_in[6],  (const float*)d_in[10], (const float*)d_in[14] };
    const float* bt[3] = { (const float*)d_in[7],  (const float*)d_in[11], (const float*)d_in[15] };

    int n = in_sizes[0] / 128;    // 100000
    int E = in_sizes[1] / 2;      // 1000000
    float* out = (float*)d_out;

    int nb512 = (n + 511) / 512;
    int gemm_blocks = (n + 127) / 128;
    int agg_blocks = (n + 31) / 32;     // 4 nodes per warp, 8 warps per block

    cudaStream_t s2;
    cudaEvent_t evFork, evScan1, evJoin;
    bool forked = (cudaStreamCreateWithFlags(&s2, cudaStreamNonBlocking) == cudaSuccess);
    if (forked) {
        cudaEventCreateWithFlags(&evFork,  cudaEventDisableTiming);
        cudaEventCreateWithFlags(&evScan1, cudaEventDisableTiming);
        cudaEventCreateWithFlags(&evJoin,  cudaEventDisableTiming);
        cudaEventRecord(evFork, 0);
        cudaStreamWaitEvent(s2, evFork, 0);
    }
    cudaStream_t sp = forked ? s2 : (cudaStream_t)0;

    k_zero_detect<<<(n + 255) / 256, 256>>>((const unsigned long long*)ei, n);
    k_hist<<<(E + 255) / 256, 256>>>(ei, E);
    k_scan1<<<nb512, 512>>>(n);                         // produces g_dinv + g_part
    if (forked) cudaEventRecord(evScan1, 0);

    // fork branch: proj GEMM, then layer-0 GEMM (needs g_H + g_dinv, not edges)
    k_tgemm<<<gemm_blocks, 256, 0, sp>>>(x, proj_w, proj_b, /*dst=*/0, n, 128);
    if (forked) cudaStreamWaitEvent(s2, evScan1, 0);
    k_tgemm<<<gemm_blocks, 256, 0, sp>>>(nullptr, w[0], nullptr, /*dst=*/1, n, 64);

    k_scan23<<<nb512, 512>>>(n);
    k_place<<<(E + 255) / 256, 256>>>(ei, E);

    if (forked) {
        cudaEventRecord(evJoin, s2);
        cudaStreamWaitEvent(0, evJoin, 0);
    }

    for (int l = 0; l < 3; l++) {
        if (l > 0)
            k_tgemm<<<gemm_blocks, 256>>>(nullptr, w[l], nullptr, /*dst=*/1, n, 64);
        float* dst = (l < 2) ? nullptr : out;
        k_agg<<<agg_blocks, 256>>>(b[l], gm[l], bt[l], dst, n, (l < 2) ? 1 : 0);
    }

    if (forked) {
        cudaStreamDestroy(s2);
        cudaEventDestroy(evFork);
        cudaEventDestroy(evScan1);
        cudaEventDestroy(evJoin);
    }
}